// round 1
// baseline (speedup 1.0000x reference)
#include <cuda_runtime.h>
#include <cstdint>
#include <math.h>

// Problem constants
#define BB   4096
#define NSEQ 25
#define DD   256
#define HHH  8
#define DQF  64
#define MROWS (BB * NSEQ)          // 102400
#define KKIM  768                  // im2col K = 3*256

// ---------------- device scratch (no cudaMalloc allowed) ----------------
__device__ float g_q [MROWS * DD];
__device__ float g_k [MROWS * DD];
__device__ float g_v [MROWS * DD];
__device__ float g_qf[MROWS * DQF];
__device__ float g_wT[3 * KKIM * DD];   // transposed conv weights: [proj][kk][o]

// ---------------- kernel 0: weight transpose (im2col layout) ----------------
// wT[proj][kk][o] = w[o][ci][k3]  with kk = k3*256 + ci
__global__ void wt_kernel(const float* __restrict__ wq,
                          const float* __restrict__ wk,
                          const float* __restrict__ wv) {
    int proj = blockIdx.y;
    int kk   = blockIdx.x;                 // 0..767
    int o    = threadIdx.x;                // 0..255
    const float* w = (proj == 0) ? wq : (proj == 1) ? wk : wv;
    int k3 = kk >> 8;
    int ci = kk & 255;
    g_wT[((size_t)proj * KKIM + kk) * DD + o] = w[(size_t)o * KKIM + ci * 3 + k3];
}

// ---------------- kernel 1: conv GEMM + LayerNorm + residual ----------------
struct ConvArgs {
    const float* x;
    const float* gam[3];
    const float* bet[3];
};

// Tile: 64 rows x 256 cols, K-chunks of 32. 256 threads, 8x8 register block.
__global__ void __launch_bounds__(256, 2) conv_ln_kernel(ConvArgs a) {
    __shared__ float XsT[32][64];    // transposed x chunk: [kk_local][row]
    __shared__ float Ws [32][256];   // weight chunk: [kk_local][col]

    const int proj = blockIdx.y;
    const int row0 = blockIdx.x * 64;
    const int tid  = threadIdx.x;
    const int cg   = tid & 31;       // column lane (0..31)
    const int rg   = tid >> 5;       // row group   (0..7)

    float* outp = (proj == 0) ? g_q : (proj == 1) ? g_k : g_v;
    const float* wT = g_wT + (size_t)proj * KKIM * DD;

    float acc[8][8];
#pragma unroll
    for (int r = 0; r < 8; r++)
#pragma unroll
        for (int u = 0; u < 8; u++) acc[r][u] = 0.f;

    // loader mapping: each thread loads 8 consecutive kk for one row
    const int lrow = tid >> 2;               // 0..63
    const int lcl  = (tid & 3) * 8;          // 0,8,16,24
    const int grow_l = row0 + lrow;
    const int n_l    = grow_l % NSEQ;

    for (int kk0 = 0; kk0 < KKIM; kk0 += 32) {
        const int k3  = kk0 >> 8;            // chunk never straddles k3
        const int ci0 = kk0 & 255;
        // --- load X chunk (im2col, zero-padded), store transposed ---
        {
            const int np = n_l + k3 - 1;
            float4 v0 = make_float4(0.f, 0.f, 0.f, 0.f);
            float4 v1 = make_float4(0.f, 0.f, 0.f, 0.f);
            if (np >= 0 && np < NSEQ) {
                const float4* src = (const float4*)(a.x + (size_t)(grow_l + k3 - 1) * DD + ci0 + lcl);
                v0 = src[0]; v1 = src[1];
            }
            XsT[lcl + 0][lrow] = v0.x; XsT[lcl + 1][lrow] = v0.y;
            XsT[lcl + 2][lrow] = v0.z; XsT[lcl + 3][lrow] = v0.w;
            XsT[lcl + 4][lrow] = v1.x; XsT[lcl + 5][lrow] = v1.y;
            XsT[lcl + 6][lrow] = v1.z; XsT[lcl + 7][lrow] = v1.w;
        }
        // --- load W chunk (coalesced float4) ---
        {
            const float4* wsrc = (const float4*)(wT + (size_t)kk0 * DD);
            float4* wdst = (float4*)&Ws[0][0];
#pragma unroll
            for (int u = 0; u < 8; u++) wdst[tid + u * 256] = wsrc[tid + u * 256];
        }
        __syncthreads();
        // --- FFMA mainloop ---
#pragma unroll
        for (int kl = 0; kl < 32; kl++) {
            float4 a0 = *(const float4*)&XsT[kl][rg * 8];
            float4 a1 = *(const float4*)&XsT[kl][rg * 8 + 4];
            float av[8] = {a0.x, a0.y, a0.z, a0.w, a1.x, a1.y, a1.z, a1.w};
            float bv[8];
#pragma unroll
            for (int u = 0; u < 8; u++) bv[u] = Ws[kl][cg + 32 * u];
#pragma unroll
            for (int r = 0; r < 8; r++)
#pragma unroll
                for (int u = 0; u < 8; u++)
                    acc[r][u] = fmaf(av[r], bv[u], acc[r][u]);
        }
        __syncthreads();
    }

    // --- LayerNorm + residual epilogue (full row lives in one warp) ---
    float gm[8], bt[8];
#pragma unroll
    for (int u = 0; u < 8; u++) {
        gm[u] = __ldg(a.gam[proj] + cg + 32 * u);
        bt[u] = __ldg(a.bet[proj] + cg + 32 * u);
    }
#pragma unroll
    for (int r = 0; r < 8; r++) {
        float s = 0.f, s2 = 0.f;
#pragma unroll
        for (int u = 0; u < 8; u++) { float v = acc[r][u]; s += v; s2 = fmaf(v, v, s2); }
#pragma unroll
        for (int off = 16; off > 0; off >>= 1) {
            s  += __shfl_xor_sync(0xffffffffu, s,  off);
            s2 += __shfl_xor_sync(0xffffffffu, s2, off);
        }
        const float mu   = s  * (1.f / 256.f);
        const float var  = s2 * (1.f / 256.f) - mu * mu;
        const float rstd = rsqrtf(var + 1e-5f);
        const int grow = row0 + rg * 8 + r;
        const float* xr = a.x + (size_t)grow * DD;
        float* orow = outp + (size_t)grow * DD;
#pragma unroll
        for (int u = 0; u < 8; u++) {
            const int c = cg + 32 * u;
            orow[c] = xr[c] + (acc[r][u] - mu) * rstd * gm[u] + bt[u];
        }
    }
}

// ---------------- kernel 2: qf = x @ wqf + bqf ----------------
// Tile: 64 rows x 64 cols. 256 threads; thread = (row-quarter, col), 16 rows each.
__global__ void __launch_bounds__(256, 2) qf_kernel(const float* __restrict__ x,
                                                    const float* __restrict__ wqf,
                                                    const float* __restrict__ bqf) {
    __shared__ float Xs[64][32];
    const int tid  = threadIdx.x;
    const int col  = tid & 63;
    const int rq   = tid >> 6;                 // 0..3
    const int row0 = blockIdx.x * 64;

    float acc[16];
#pragma unroll
    for (int r = 0; r < 16; r++) acc[r] = 0.f;

    const int lrow = tid >> 2;
    const int lcl  = (tid & 3) * 8;

    for (int c0 = 0; c0 < 256; c0 += 32) {
        const float4* src = (const float4*)(x + (size_t)(row0 + lrow) * DD + c0 + lcl);
        float4 v0 = src[0], v1 = src[1];
        *(float4*)&Xs[lrow][lcl]     = v0;
        *(float4*)&Xs[lrow][lcl + 4] = v1;
        __syncthreads();
#pragma unroll
        for (int c4 = 0; c4 < 8; c4++) {
            float w0 = __ldg(wqf + (size_t)(c0 + c4 * 4 + 0) * DQF + col);
            float w1 = __ldg(wqf + (size_t)(c0 + c4 * 4 + 1) * DQF + col);
            float w2 = __ldg(wqf + (size_t)(c0 + c4 * 4 + 2) * DQF + col);
            float w3 = __ldg(wqf + (size_t)(c0 + c4 * 4 + 3) * DQF + col);
#pragma unroll
            for (int r = 0; r < 16; r++) {
                float4 xv = *(const float4*)&Xs[rq * 16 + r][c4 * 4];
                acc[r] = fmaf(xv.x, w0, fmaf(xv.y, w1, fmaf(xv.z, w2, fmaf(xv.w, w3, acc[r]))));
            }
        }
        __syncthreads();
    }
    const float bb = __ldg(bqf + col);
#pragma unroll
    for (int r = 0; r < 16; r++)
        g_qf[(size_t)(row0 + rq * 16 + r) * DQF + col] = acc[r] + bb;
}

// ---------------- kernel 3: fused attention (one CTA per batch) ----------------
struct AttnArgs {
    const float* rel;     // [49, 8]
    const float* gb;      // [8, 25, 25]
    const float* alpha;   // scalar
    const float* wqp;     // [64, 8]
    const float* bqp;     // [8]
    const float* wo;      // [256, 256]
    const float* bo;      // [256]
    float*       out;     // [B, 25, 256]
};

// smem float offsets
#define SOFF_QS   0            // 6400  (reused as ctx after scores)
#define SOFF_VS   6400         // 6400
#define SOFF_KT   12800        // 256*28 = 7168
#define SOFF_QF   19968        // 25*65 = 1625
#define SOFF_SS   21593        // 5000
#define SOFF_WQP  26593        // 64*9 = 576
#define SOFF_REL  27169        // 392
#define SOFF_BQP  27561        // 8
#define SMEM_C_FLOATS 27569
#define SMEM_C_BYTES  (SMEM_C_FLOATS * 4)

__global__ void __launch_bounds__(256, 2) attn_kernel(AttnArgs a) {
    extern __shared__ float sm[];
    float* qs   = sm + SOFF_QS;
    float* vs   = sm + SOFF_VS;
    float* kT   = sm + SOFF_KT;    // [256][28] (d-major, j fast)
    float* qfs  = sm + SOFF_QF;    // [25][65]
    float* ss   = sm + SOFF_SS;    // [8][25][25]
    float* wqps = sm + SOFF_WQP;   // [64][9]
    float* rels = sm + SOFF_REL;   // [49][8]
    float* bqps = sm + SOFF_BQP;   // [8]

    const int b   = blockIdx.x;
    const int tid = threadIdx.x;

    const float* qb  = g_q  + (size_t)b * (NSEQ * DD);
    const float* kb  = g_k  + (size_t)b * (NSEQ * DD);
    const float* vb  = g_v  + (size_t)b * (NSEQ * DD);
    const float* qfb = g_qf + (size_t)b * (NSEQ * DQF);

    // ---- stage loads ----
    for (int i = tid; i < 1600; i += 256) {
        ((float4*)qs)[i] = ((const float4*)qb)[i];
        ((float4*)vs)[i] = ((const float4*)vb)[i];
    }
    for (int i = tid; i < 6400; i += 256) {   // k transposed: kT[d][j]
        int j = i >> 8, d = i & 255;
        kT[d * 28 + j] = kb[i];
    }
    for (int i = tid; i < 400; i += 256) {    // qf, rows padded to 65
        float4 t = ((const float4*)qfb)[i];
        int r = i >> 4, c = (i & 15) * 4;
        float* dst = &qfs[r * 65 + c];
        dst[0] = t.x; dst[1] = t.y; dst[2] = t.z; dst[3] = t.w;
    }
    for (int i = tid; i < 512; i += 256)      // wqp, rows padded to 9
        wqps[(i >> 3) * 9 + (i & 7)] = a.wqp[i];
    for (int i = tid; i < 392; i += 256) rels[i] = a.rel[i];
    if (tid < 8) bqps[tid] = a.bqp[tid];
    const float alpha = __ldg(a.alpha);
    __syncthreads();

    // ---- scores: q.k / sqrt(dk) + rel_bias + global_bias*alpha ----
    for (int idx = tid; idx < 5000; idx += 256) {
        const int h   = idx / 625;
        const int rem = idx - h * 625;
        const int i   = rem / 25;
        const int j   = rem - i * 25;
        const float* qr = qs + i * DD + h * 32;
        const float* kc = kT + (h * 32) * 28 + j;
        float s = 0.f;
#pragma unroll
        for (int d4 = 0; d4 < 8; d4++) {
            float4 qv = *(const float4*)(qr + d4 * 4);
            s = fmaf(qv.x, kc[(d4 * 4 + 0) * 28],
                fmaf(qv.y, kc[(d4 * 4 + 1) * 28],
                fmaf(qv.z, kc[(d4 * 4 + 2) * 28],
                fmaf(qv.w, kc[(d4 * 4 + 3) * 28], s))));
        }
        s *= 0.17677669529663687f;                 // 1/sqrt(32)
        s += rels[(i - j + 24) * 8 + h];
        s += __ldg(a.gb + idx) * alpha;            // gb layout [h][i][j] == idx
        ss[idx] = s;
    }
    __syncthreads();

    // ---- dynamic adjacency bias: sum_c tanh(qf[i]-qf[j]) * wqp[c][h] ----
    {
        const int warp = tid >> 5, lane = tid & 31;
        for (int i = warp; i < NSEQ; i += 8) {
            if (lane < NSEQ) {
                const int j = lane;
                float acc[8];
#pragma unroll
                for (int h = 0; h < 8; h++) acc[h] = 0.f;
#pragma unroll 4
                for (int c = 0; c < DQF; c++) {
                    float t = tanhf(qfs[i * 65 + c] - qfs[j * 65 + c]);
#pragma unroll
                    for (int h = 0; h < 8; h++)
                        acc[h] = fmaf(t, wqps[c * 9 + h], acc[h]);
                }
#pragma unroll
                for (int h = 0; h < 8; h++)
                    ss[h * 625 + i * 25 + j] += acc[h] + bqps[h];
            }
        }
    }
    __syncthreads();

    // ---- softmax over j (200 rows) ----
    if (tid < 200) {
        const int h = tid / 25, i = tid - h * 25;
        float* row = ss + h * 625 + i * 25;
        float m = row[0];
#pragma unroll
        for (int j = 1; j < 25; j++) m = fmaxf(m, row[j]);
        float sum = 0.f;
#pragma unroll
        for (int j = 0; j < 25; j++) { float e = expf(row[j] - m); row[j] = e; sum += e; }
        const float inv = 1.f / sum;
#pragma unroll
        for (int j = 0; j < 25; j++) row[j] *= inv;
    }
    __syncthreads();

    // ---- ctx = attn @ v  (writes into qs region, q is dead) ----
    float* cs = qs;
    {
        const int h = tid >> 5;
        float acc[25];
#pragma unroll
        for (int i = 0; i < 25; i++) acc[i] = 0.f;
        for (int j = 0; j < 25; j++) {
            const float vv = vs[j * DD + tid];
#pragma unroll
            for (int i = 0; i < 25; i++)
                acc[i] = fmaf(ss[h * 625 + i * 25 + j], vv, acc[i]);
        }
#pragma unroll
        for (int i = 0; i < 25; i++) cs[i * DD + tid] = acc[i];
    }
    __syncthreads();

    // ---- out = ctx @ wo + bo ----
    {
        float acc[25];
#pragma unroll
        for (int i = 0; i < 25; i++) acc[i] = 0.f;
        for (int c = 0; c < 256; c += 4) {
            const float w0 = __ldg(a.wo + (size_t)(c + 0) * DD + tid);
            const float w1 = __ldg(a.wo + (size_t)(c + 1) * DD + tid);
            const float w2 = __ldg(a.wo + (size_t)(c + 2) * DD + tid);
            const float w3 = __ldg(a.wo + (size_t)(c + 3) * DD + tid);
#pragma unroll
            for (int i = 0; i < 25; i++) {
                float4 cv = *(const float4*)&cs[i * DD + c];
                acc[i] = fmaf(cv.x, w0, fmaf(cv.y, w1, fmaf(cv.z, w2, fmaf(cv.w, w3, acc[i]))));
            }
        }
        const float bb = __ldg(a.bo + tid);
        float* ob = a.out + (size_t)b * (NSEQ * DD);
#pragma unroll
        for (int i = 0; i < 25; i++) ob[i * DD + tid] = acc[i] + bb;
    }
}

// ---------------- launch ----------------
extern "C" void kernel_launch(void* const* d_in, const int* in_sizes, int n_in,
                              void* d_out, int out_size) {
    const float* x      = (const float*)d_in[0];
    const float* wq     = (const float*)d_in[1];
    const float* wk     = (const float*)d_in[2];
    const float* wv     = (const float*)d_in[3];
    const float* ln_q_g = (const float*)d_in[4];
    const float* ln_q_b = (const float*)d_in[5];
    const float* ln_k_g = (const float*)d_in[6];
    const float* ln_k_b = (const float*)d_in[7];
    const float* ln_v_g = (const float*)d_in[8];
    const float* ln_v_b = (const float*)d_in[9];
    const float* rel    = (const float*)d_in[10];
    const float* gb     = (const float*)d_in[11];
    const float* alpha  = (const float*)d_in[12];
    const float* wqf    = (const float*)d_in[13];
    const float* bqf    = (const float*)d_in[14];
    const float* wqp    = (const float*)d_in[15];
    const float* bqp    = (const float*)d_in[16];
    const float* wo     = (const float*)d_in[17];
    const float* bo     = (const float*)d_in[18];
    float* out = (float*)d_out;

    cudaFuncSetAttribute(attn_kernel, cudaFuncAttributeMaxDynamicSharedMemorySize, SMEM_C_BYTES);

    wt_kernel<<<dim3(768, 3), 256>>>(wq, wk, wv);

    ConvArgs ca;
    ca.x = x;
    ca.gam[0] = ln_q_g; ca.gam[1] = ln_k_g; ca.gam[2] = ln_v_g;
    ca.bet[0] = ln_q_b; ca.bet[1] = ln_k_b; ca.bet[2] = ln_v_b;
    conv_ln_kernel<<<dim3(MROWS / 64, 3), 256>>>(ca);

    qf_kernel<<<MROWS / 64, 256>>>(x, wqf, bqf);

    AttnArgs aa;
    aa.rel = rel; aa.gb = gb; aa.alpha = alpha;
    aa.wqp = wqp; aa.bqp = bqp; aa.wo = wo; aa.bo = bo; aa.out = out;
    attn_kernel<<<BB, 256, SMEM_C_BYTES>>>(aa);
}

// round 16
// speedup vs baseline: 1.0390x; 1.0390x over previous
#include <cuda_runtime.h>
#include <cstdint>
#include <math.h>

// Problem constants
#define BB   4096
#define NSEQ 25
#define DD   256
#define HHH  8
#define DQF  64
#define MROWS (BB * NSEQ)          // 102400
#define KKIM  768                  // im2col K = 3*256

typedef unsigned long long ull;

// ---------------- packed f32x2 helpers (Blackwell FFMA2) ----------------
__device__ __forceinline__ ull pack2(float lo, float hi) {
    ull r;
    asm("mov.b64 %0, {%1, %2};" : "=l"(r) : "f"(lo), "f"(hi));
    return r;
}
__device__ __forceinline__ void unpack2(ull v, float& lo, float& hi) {
    asm("mov.b64 {%0, %1}, %2;" : "=f"(lo), "=f"(hi) : "l"(v));
}
__device__ __forceinline__ ull ffma2(ull a, ull b, ull c) {
    ull d;
    asm("fma.rn.f32x2 %0, %1, %2, %3;" : "=l"(d) : "l"(a), "l"(b), "l"(c));
    return d;
}

// ---------------- device scratch (no cudaMalloc allowed) ----------------
__device__ float g_q  [MROWS * DD];
__device__ float g_k  [MROWS * DD];
__device__ float g_v  [MROWS * DD];
__device__ float g_qf [MROWS * DQF];
__device__ float g_ctx[MROWS * DD];
__device__ float g_wT [3 * KKIM * DD];   // transposed conv weights: [proj][kk][o]

// ---------------- kernel 0: weight transpose (im2col layout) ----------------
__global__ void wt_kernel(const float* __restrict__ wq,
                          const float* __restrict__ wk,
                          const float* __restrict__ wv) {
    int proj = blockIdx.y;
    int kk   = blockIdx.x;                 // 0..767
    int o    = threadIdx.x;                // 0..255
    const float* w = (proj == 0) ? wq : (proj == 1) ? wk : wv;
    int k3 = kk >> 8;
    int ci = kk & 255;
    g_wT[((size_t)proj * KKIM + kk) * DD + o] = w[(size_t)o * KKIM + ci * 3 + k3];
}

// ---------------- kernel 1: conv GEMM + LayerNorm + residual (FFMA2) ----------------
struct ConvArgs {
    const float* x;
    const float* gam[3];
    const float* bet[3];
};

// Tile: 64 rows x 256 cols, K-chunks of 32. 256 threads, 8x8 register block,
// packed f32x2 accumulation (acc2[r][u2]: lo -> col cg+64*u2, hi -> col cg+64*u2+32).
__global__ void __launch_bounds__(256, 2) conv_ln_kernel(ConvArgs a) {
    __shared__ float XsT[32][64];    // transposed x chunk: [kk_local][row]
    __shared__ float Ws [32][256];   // weight chunk: [kk_local][col]

    const int proj = blockIdx.y;
    const int row0 = blockIdx.x * 64;
    const int tid  = threadIdx.x;
    const int cg   = tid & 31;       // column lane (0..31)
    const int rg   = tid >> 5;       // row group   (0..7)

    float* outp = (proj == 0) ? g_q : (proj == 1) ? g_k : g_v;
    const float* wT = g_wT + (size_t)proj * KKIM * DD;

    ull acc2[8][4];
#pragma unroll
    for (int r = 0; r < 8; r++)
#pragma unroll
        for (int u2 = 0; u2 < 4; u2++) acc2[r][u2] = 0ull;

    const int lrow = tid >> 2;               // 0..63
    const int lcl  = (tid & 3) * 8;          // 0,8,16,24
    const int grow_l = row0 + lrow;
    const int n_l    = grow_l % NSEQ;

    for (int kk0 = 0; kk0 < KKIM; kk0 += 32) {
        const int k3  = kk0 >> 8;            // chunk never straddles k3
        const int ci0 = kk0 & 255;
        // --- load X chunk (im2col, zero-padded), store transposed ---
        {
            const int np = n_l + k3 - 1;
            float4 v0 = make_float4(0.f, 0.f, 0.f, 0.f);
            float4 v1 = make_float4(0.f, 0.f, 0.f, 0.f);
            if (np >= 0 && np < NSEQ) {
                const float4* src = (const float4*)(a.x + (size_t)(grow_l + k3 - 1) * DD + ci0 + lcl);
                v0 = src[0]; v1 = src[1];
            }
            XsT[lcl + 0][lrow] = v0.x; XsT[lcl + 1][lrow] = v0.y;
            XsT[lcl + 2][lrow] = v0.z; XsT[lcl + 3][lrow] = v0.w;
            XsT[lcl + 4][lrow] = v1.x; XsT[lcl + 5][lrow] = v1.y;
            XsT[lcl + 6][lrow] = v1.z; XsT[lcl + 7][lrow] = v1.w;
        }
        // --- load W chunk (coalesced float4) ---
        {
            const float4* wsrc = (const float4*)(wT + (size_t)kk0 * DD);
            float4* wdst = (float4*)&Ws[0][0];
#pragma unroll
            for (int u = 0; u < 8; u++) wdst[tid + u * 256] = wsrc[tid + u * 256];
        }
        __syncthreads();
        // --- FFMA2 mainloop ---
#pragma unroll
        for (int kl = 0; kl < 32; kl++) {
            float4 a0 = *(const float4*)&XsT[kl][rg * 8];
            float4 a1 = *(const float4*)&XsT[kl][rg * 8 + 4];
            ull ap[8];
            ap[0] = pack2(a0.x, a0.x); ap[1] = pack2(a0.y, a0.y);
            ap[2] = pack2(a0.z, a0.z); ap[3] = pack2(a0.w, a0.w);
            ap[4] = pack2(a1.x, a1.x); ap[5] = pack2(a1.y, a1.y);
            ap[6] = pack2(a1.z, a1.z); ap[7] = pack2(a1.w, a1.w);
            ull bv2[4];
#pragma unroll
            for (int u2 = 0; u2 < 4; u2++)
                bv2[u2] = pack2(Ws[kl][cg + 64 * u2], Ws[kl][cg + 64 * u2 + 32]);
#pragma unroll
            for (int r = 0; r < 8; r++)
#pragma unroll
                for (int u2 = 0; u2 < 4; u2++)
                    acc2[r][u2] = ffma2(ap[r], bv2[u2], acc2[r][u2]);
        }
        __syncthreads();
    }

    // --- LayerNorm + residual epilogue ---
    float gm[8], bt[8];
#pragma unroll
    for (int u = 0; u < 8; u++) {
        gm[u] = __ldg(a.gam[proj] + cg + 32 * u);
        bt[u] = __ldg(a.bet[proj] + cg + 32 * u);
    }
#pragma unroll
    for (int r = 0; r < 8; r++) {
        float acc[8];
#pragma unroll
        for (int u2 = 0; u2 < 4; u2++)
            unpack2(acc2[r][u2], acc[2 * u2], acc[2 * u2 + 1]);
        float s = 0.f, s2 = 0.f;
#pragma unroll
        for (int u = 0; u < 8; u++) { float v = acc[u]; s += v; s2 = fmaf(v, v, s2); }
#pragma unroll
        for (int off = 16; off > 0; off >>= 1) {
            s  += __shfl_xor_sync(0xffffffffu, s,  off);
            s2 += __shfl_xor_sync(0xffffffffu, s2, off);
        }
        const float mu   = s  * (1.f / 256.f);
        const float var  = s2 * (1.f / 256.f) - mu * mu;
        const float rstd = rsqrtf(var + 1e-5f);
        const int grow = row0 + rg * 8 + r;
        const float* xr = a.x + (size_t)grow * DD;
        float* orow = outp + (size_t)grow * DD;
        // column mapping: u=2*u2 -> cg+64*u2 ; u=2*u2+1 -> cg+64*u2+32  == cg+32*u
#pragma unroll
        for (int u = 0; u < 8; u++) {
            const int c = cg + 32 * u;
            orow[c] = xr[c] + (acc[u] - mu) * rstd * gm[u] + bt[u];
        }
    }
}

// ---------------- kernel 2: qf = x @ wqf + bqf ----------------
__global__ void __launch_bounds__(256, 2) qf_kernel(const float* __restrict__ x,
                                                    const float* __restrict__ wqf,
                                                    const float* __restrict__ bqf) {
    __shared__ float Xs[64][32];
    const int tid  = threadIdx.x;
    const int col  = tid & 63;
    const int rq   = tid >> 6;                 // 0..3
    const int row0 = blockIdx.x * 64;

    float acc[16];
#pragma unroll
    for (int r = 0; r < 16; r++) acc[r] = 0.f;

    const int lrow = tid >> 2;
    const int lcl  = (tid & 3) * 8;

    for (int c0 = 0; c0 < 256; c0 += 32) {
        const float4* src = (const float4*)(x + (size_t)(row0 + lrow) * DD + c0 + lcl);
        float4 v0 = src[0], v1 = src[1];
        *(float4*)&Xs[lrow][lcl]     = v0;
        *(float4*)&Xs[lrow][lcl + 4] = v1;
        __syncthreads();
#pragma unroll
        for (int c4 = 0; c4 < 8; c4++) {
            float w0 = __ldg(wqf + (size_t)(c0 + c4 * 4 + 0) * DQF + col);
            float w1 = __ldg(wqf + (size_t)(c0 + c4 * 4 + 1) * DQF + col);
            float w2 = __ldg(wqf + (size_t)(c0 + c4 * 4 + 2) * DQF + col);
            float w3 = __ldg(wqf + (size_t)(c0 + c4 * 4 + 3) * DQF + col);
#pragma unroll
            for (int r = 0; r < 16; r++) {
                float4 xv = *(const float4*)&Xs[rq * 16 + r][c4 * 4];
                acc[r] = fmaf(xv.x, w0, fmaf(xv.y, w1, fmaf(xv.z, w2, fmaf(xv.w, w3, acc[r]))));
            }
        }
        __syncthreads();
    }
    const float bb = __ldg(bqf + col);
#pragma unroll
    for (int r = 0; r < 16; r++)
        g_qf[(size_t)(row0 + rq * 16 + r) * DQF + col] = acc[r] + bb;
}

// ---------------- kernel 3: fused attention core (one CTA per batch) ----------------
// q read via broadcast __ldg; v streamed coalesced in ctx stage; ctx -> gmem.
struct AttnArgs {
    const float* rel;     // [49, 8]
    const float* gb;      // [8, 25, 25]
    const float* alpha;   // scalar
    const float* wqp;     // [64, 8]
    const float* bqp;     // [8]
};

// smem float offsets (59 KB total -> 3 CTAs/SM)
#define SOFF_KT   0            // 256*28 = 7168
#define SOFF_QF   7168         // 25*65  = 1625
#define SOFF_SS   8793         // 5000
#define SOFF_WQP  13793        // 64*9   = 576
#define SOFF_REL  14369        // 392
#define SOFF_BQP  14761        // 8
#define SMEM_C_FLOATS 14769
#define SMEM_C_BYTES  (SMEM_C_FLOATS * 4)

__global__ void __launch_bounds__(256, 3) attn_kernel(AttnArgs a) {
    extern __shared__ float sm[];
    float* kT   = sm + SOFF_KT;    // [256][28] (d-major, j fast)
    float* qfs  = sm + SOFF_QF;    // [25][65]
    float* ss   = sm + SOFF_SS;    // [8][25][25]
    float* wqps = sm + SOFF_WQP;   // [64][9]
    float* rels = sm + SOFF_REL;   // [49][8]
    float* bqps = sm + SOFF_BQP;   // [8]

    const int b   = blockIdx.x;
    const int tid = threadIdx.x;

    const float* qb  = g_q  + (size_t)b * (NSEQ * DD);
    const float* kb  = g_k  + (size_t)b * (NSEQ * DD);
    const float* vb  = g_v  + (size_t)b * (NSEQ * DD);
    const float* qfb = g_qf + (size_t)b * (NSEQ * DQF);

    // ---- stage loads ----
    for (int i = tid; i < 6400; i += 256) {   // k transposed: kT[d][j]
        int j = i >> 8, d = i & 255;
        kT[d * 28 + j] = kb[i];
    }
    for (int i = tid; i < 400; i += 256) {    // qf, rows padded to 65
        float4 t = ((const float4*)qfb)[i];
        int r = i >> 4, c = (i & 15) * 4;
        float* dst = &qfs[r * 65 + c];
        dst[0] = t.x; dst[1] = t.y; dst[2] = t.z; dst[3] = t.w;
    }
    for (int i = tid; i < 512; i += 256)      // wqp, rows padded to 9
        wqps[(i >> 3) * 9 + (i & 7)] = a.wqp[i];
    for (int i = tid; i < 392; i += 256) rels[i] = a.rel[i];
    if (tid < 8) bqps[tid] = a.bqp[tid];
    const float alpha = __ldg(a.alpha);
    __syncthreads();

    // ---- scores: q.k / sqrt(dk) + rel_bias + global_bias*alpha ----
    for (int idx = tid; idx < 5000; idx += 256) {
        const int h   = idx / 625;
        const int rem = idx - h * 625;
        const int i   = rem / 25;
        const int j   = rem - i * 25;
        const float4* qr = (const float4*)(qb + i * DD + h * 32);
        const float* kc = kT + (h * 32) * 28 + j;
        float s = 0.f;
#pragma unroll
        for (int d4 = 0; d4 < 8; d4++) {
            float4 qv = __ldg(qr + d4);
            s = fmaf(qv.x, kc[(d4 * 4 + 0) * 28],
                fmaf(qv.y, kc[(d4 * 4 + 1) * 28],
                fmaf(qv.z, kc[(d4 * 4 + 2) * 28],
                fmaf(qv.w, kc[(d4 * 4 + 3) * 28], s))));
        }
        s *= 0.17677669529663687f;                 // 1/sqrt(32)
        s += rels[(i - j + 24) * 8 + h];
        s += __ldg(a.gb + idx) * alpha;            // gb layout [h][i][j] == idx
        ss[idx] = s;
    }
    __syncthreads();

    // ---- dynamic adjacency bias: sum_c tanh(qf[i]-qf[j]) * wqp[c][h] ----
    {
        const int warp = tid >> 5, lane = tid & 31;
        for (int i = warp; i < NSEQ; i += 8) {
            if (lane < NSEQ) {
                const int j = lane;
                float acc[8];
#pragma unroll
                for (int h = 0; h < 8; h++) acc[h] = 0.f;
#pragma unroll 4
                for (int c = 0; c < DQF; c++) {
                    float t = tanhf(qfs[i * 65 + c] - qfs[j * 65 + c]);
#pragma unroll
                    for (int h = 0; h < 8; h++)
                        acc[h] = fmaf(t, wqps[c * 9 + h], acc[h]);
                }
#pragma unroll
                for (int h = 0; h < 8; h++)
                    ss[h * 625 + i * 25 + j] += acc[h] + bqps[h];
            }
        }
    }
    __syncthreads();

    // ---- softmax over j (200 rows) ----
    if (tid < 200) {
        const int h = tid / 25, i = tid - h * 25;
        float* row = ss + h * 625 + i * 25;
        float m = row[0];
#pragma unroll
        for (int j = 1; j < 25; j++) m = fmaxf(m, row[j]);
        float sum = 0.f;
#pragma unroll
        for (int j = 0; j < 25; j++) { float e = expf(row[j] - m); row[j] = e; sum += e; }
        const float inv = 1.f / sum;
#pragma unroll
        for (int j = 0; j < 25; j++) row[j] *= inv;
    }
    __syncthreads();

    // ---- ctx = attn @ v  (v streamed from gmem, ctx -> gmem) ----
    {
        const int h = tid >> 5;
        float acc[25];
#pragma unroll
        for (int i = 0; i < 25; i++) acc[i] = 0.f;
        for (int j = 0; j < 25; j++) {
            const float vv = __ldg(vb + j * DD + tid);
            const float* sr = ss + h * 625 + j;
#pragma unroll
            for (int i = 0; i < 25; i++)
                acc[i] = fmaf(sr[i * 25], vv, acc[i]);
        }
        float* cb = g_ctx + (size_t)b * (NSEQ * DD);
#pragma unroll
        for (int i = 0; i < 25; i++) cb[i * DD + tid] = acc[i];
    }
}

// ---------------- kernel 4: out = ctx @ wo + bo (FFMA2 GEMM) ----------------
__global__ void __launch_bounds__(256, 2) out_gemm_kernel(const float* __restrict__ wo,
                                                          const float* __restrict__ bo,
                                                          float* __restrict__ out) {
    __shared__ float XsT[32][64];
    __shared__ float Ws [32][256];

    const int row0 = blockIdx.x * 64;
    const int tid  = threadIdx.x;
    const int cg   = tid & 31;
    const int rg   = tid >> 5;

    ull acc2[8][4];
#pragma unroll
    for (int r = 0; r < 8; r++)
#pragma unroll
        for (int u2 = 0; u2 < 4; u2++) acc2[r][u2] = 0ull;

    const int lrow = tid >> 2;
    const int lcl  = (tid & 3) * 8;

    for (int c0 = 0; c0 < 256; c0 += 32) {
        // --- stage ctx chunk transposed ---
        {
            const float4* src = (const float4*)(g_ctx + (size_t)(row0 + lrow) * DD + c0 + lcl);
            float4 v0 = src[0], v1 = src[1];
            XsT[lcl + 0][lrow] = v0.x; XsT[lcl + 1][lrow] = v0.y;
            XsT[lcl + 2][lrow] = v0.z; XsT[lcl + 3][lrow] = v0.w;
            XsT[lcl + 4][lrow] = v1.x; XsT[lcl + 5][lrow] = v1.y;
            XsT[lcl + 6][lrow] = v1.z; XsT[lcl + 7][lrow] = v1.w;
        }
        // --- stage wo chunk (rows c0..c0+31, all 256 cols) ---
        {
            const float4* wsrc = (const float4*)(wo + (size_t)c0 * DD);
            float4* wdst = (float4*)&Ws[0][0];
#pragma unroll
            for (int u = 0; u < 8; u++) wdst[tid + u * 256] = wsrc[tid + u * 256];
        }
        __syncthreads();
#pragma unroll
        for (int kl = 0; kl < 32; kl++) {
            float4 a0 = *(const float4*)&XsT[kl][rg * 8];
            float4 a1 = *(const float4*)&XsT[kl][rg * 8 + 4];
            ull ap[8];
            ap[0] = pack2(a0.x, a0.x); ap[1] = pack2(a0.y, a0.y);
            ap[2] = pack2(a0.z, a0.z); ap[3] = pack2(a0.w, a0.w);
            ap[4] = pack2(a1.x, a1.x); ap[5] = pack2(a1.y, a1.y);
            ap[6] = pack2(a1.z, a1.z); ap[7] = pack2(a1.w, a1.w);
            ull bv2[4];
#pragma unroll
            for (int u2 = 0; u2 < 4; u2++)
                bv2[u2] = pack2(Ws[kl][cg + 64 * u2], Ws[kl][cg + 64 * u2 + 32]);
#pragma unroll
            for (int r = 0; r < 8; r++)
#pragma unroll
                for (int u2 = 0; u2 < 4; u2++)
                    acc2[r][u2] = ffma2(ap[r], bv2[u2], acc2[r][u2]);
        }
        __syncthreads();
    }

    float bt[8];
#pragma unroll
    for (int u = 0; u < 8; u++) bt[u] = __ldg(bo + cg + 32 * u);
#pragma unroll
    for (int r = 0; r < 8; r++) {
        float acc[8];
#pragma unroll
        for (int u2 = 0; u2 < 4; u2++)
            unpack2(acc2[r][u2], acc[2 * u2], acc[2 * u2 + 1]);
        const int grow = row0 + rg * 8 + r;
        float* orow = out + (size_t)grow * DD;
#pragma unroll
        for (int u = 0; u < 8; u++)
            orow[cg + 32 * u] = acc[u] + bt[u];
    }
}

// ---------------- launch ----------------
extern "C" void kernel_launch(void* const* d_in, const int* in_sizes, int n_in,
                              void* d_out, int out_size) {
    const float* x      = (const float*)d_in[0];
    const float* wq     = (const float*)d_in[1];
    const float* wk     = (const float*)d_in[2];
    const float* wv     = (const float*)d_in[3];
    const float* ln_q_g = (const float*)d_in[4];
    const float* ln_q_b = (const float*)d_in[5];
    const float* ln_k_g = (const float*)d_in[6];
    const float* ln_k_b = (const float*)d_in[7];
    const float* ln_v_g = (const float*)d_in[8];
    const float* ln_v_b = (const float*)d_in[9];
    const float* rel    = (const float*)d_in[10];
    const float* gb     = (const float*)d_in[11];
    const float* alpha  = (const float*)d_in[12];
    const float* wqf    = (const float*)d_in[13];
    const float* bqf    = (const float*)d_in[14];
    const float* wqp    = (const float*)d_in[15];
    const float* bqp    = (const float*)d_in[16];
    const float* wo     = (const float*)d_in[17];
    const float* bo     = (const float*)d_in[18];
    float* out = (float*)d_out;

    cudaFuncSetAttribute(attn_kernel, cudaFuncAttributeMaxDynamicSharedMemorySize, SMEM_C_BYTES);

    wt_kernel<<<dim3(768, 3), 256>>>(wq, wk, wv);

    ConvArgs ca;
    ca.x = x;
    ca.gam[0] = ln_q_g; ca.gam[1] = ln_k_g; ca.gam[2] = ln_v_g;
    ca.bet[0] = ln_q_b; ca.bet[1] = ln_k_b; ca.bet[2] = ln_v_b;
    conv_ln_kernel<<<dim3(MROWS / 64, 3), 256>>>(ca);

    qf_kernel<<<MROWS / 64, 256>>>(x, wqf, bqf);

    AttnArgs aa;
    aa.rel = rel; aa.gb = gb; aa.alpha = alpha;
    aa.wqp = wqp; aa.bqp = bqp;
    attn_kernel<<<BB, 256, SMEM_C_BYTES>>>(aa);

    out_gemm_kernel<<<MROWS / 64, 256>>>(wo, bo, out);
}